// round 1
// baseline (speedup 1.0000x reference)
#include <cuda_runtime.h>
#include <math.h>

// ---------------- problem constants ----------------
#define BB 2
#define LL 2048
#define DD 768
#define KK 12
#define KQn 6
#define MM 4
#define HH 64
#define MEMn 768
#define EXPn 192
#define DSWn 384
#define LATn 192
#define BL 4096            // B*L
#define ZC 780             // MEM + K
#define NCH 8
#define LC 256             // chunk length, NCH*LC == LL

// ---------------- scratch (device globals, no allocs) ----------------
__device__ float g_z0[(size_t)BL * ZC];
__device__ float g_q[(size_t)BL * 3072];
__device__ float g_gatelin[(size_t)BL * KK];
__device__ float g_lat[(size_t)BL * LATn];
__device__ float g_ydir[(size_t)BL * 4608];
__device__ float g_kval[(size_t)BB * KK * HH * LL];
__device__ float g_pw[(size_t)BB * KK * LL];
__device__ float g_theta[KK * HH * MM];
__device__ float g_wint[KK * HH * MM];
__device__ float g_slope[KK];
__device__ float g_csum[(size_t)BB * KK * HH * MM * 2 * NCH];
__device__ float g_coff[(size_t)BB * KK * HH * MM * 2 * NCH];
__device__ float g_dsum[(size_t)BB * KK * NCH];
__device__ float g_doff[(size_t)BB * KK * NCH];
__device__ float g_wcat[(size_t)KK * 128 * DSWn];
__device__ float g_A[(size_t)KK * BL * 128];
__device__ float g_yspec[(size_t)KK * BL * DSWn];
__device__ float g_yfin[(size_t)BL * 2304];

__device__ __forceinline__ float softplusf(float x) {
    return (x > 20.0f) ? x : log1pf(__expf(x));
}

// ---------------- precompute theta / w_int / slopes ----------------
__global__ void precompute_kernel(const float* __restrict__ theta_raw,
                                  const float* __restrict__ decay) {
    int tid = blockIdx.x * blockDim.x + threadIdx.x;
    if (tid < KK * HH) {
        float ta[MM];
        float run = 0.0f;
#pragma unroll
        for (int m = 0; m < MM; m++) {
            run += softplusf(theta_raw[tid * MM + m]) + 1e-4f;
            ta[m] = run;
        }
        float total = ta[MM - 1];
        float sc = 2.999f / total;   // rng / total
        float dth[MM - 1];
#pragma unroll
        for (int i = 0; i < MM - 1; i++) dth[i] = (ta[i + 1] - ta[i]) * sc;
#pragma unroll
        for (int m = 0; m < MM; m++) g_theta[tid * MM + m] = 0.001f + ta[m] * sc;
        g_wint[tid * MM + 0] = dth[0] * 0.5f;
        g_wint[tid * MM + 1] = 0.5f * (dth[0] + dth[1]);
        g_wint[tid * MM + 2] = 0.5f * (dth[1] + dth[2]);
        g_wint[tid * MM + 3] = dth[2] * 0.5f;
    }
    if (tid < KK) g_slope[tid] = softplusf(decay[tid]);
}

// ---------------- concat [W_re ; W_im] per k ----------------
__global__ void wcat_kernel(const float* __restrict__ Wre, const float* __restrict__ Wim) {
    int idx = blockIdx.x * 256 + threadIdx.x;
    if (idx >= KK * 128 * DSWn) return;
    int n = idx % DSWn;
    int r = (idx / DSWn) % 128;
    int k = idx / (128 * DSWn);
    g_wcat[idx] = (r < HH) ? Wre[((size_t)k * HH + r) * DSWn + n]
                           : Wim[((size_t)k * HH + (r - HH)) * DSWn + n];
}

// ---------------- generic SGEMM (M fixed=gridDim.y*64, always 4096) ----------
__global__ void __launch_bounds__(256) sgemm_kernel(
    const float* __restrict__ A, const float* __restrict__ Bm, float* __restrict__ C,
    int Nn, int Kk, size_t sA, size_t sB, size_t sC) {
    A += (size_t)blockIdx.z * sA;
    Bm += (size_t)blockIdx.z * sB;
    C += (size_t)blockIdx.z * sC;
    __shared__ float As[16][64];
    __shared__ float Bs[16][64];
    const int tid = threadIdx.x;
    const int tx = tid & 15, ty = tid >> 4;
    const int rowBase = blockIdx.y * 64;
    const int colBase = blockIdx.x * 64;
    const int aRow = tid >> 2, aCol = (tid & 3) * 4;
    const int bRow = tid >> 4, bCol = (tid & 15) * 4;
    float acc[4][4];
#pragma unroll
    for (int i = 0; i < 4; i++)
#pragma unroll
        for (int j = 0; j < 4; j++) acc[i][j] = 0.0f;

    for (int k0 = 0; k0 < Kk; k0 += 16) {
        float4 av = *(const float4*)(A + (size_t)(rowBase + aRow) * Kk + k0 + aCol);
        As[aCol + 0][aRow] = av.x;
        As[aCol + 1][aRow] = av.y;
        As[aCol + 2][aRow] = av.z;
        As[aCol + 3][aRow] = av.w;
        int bc = colBase + bCol;
        float4 bv = make_float4(0.f, 0.f, 0.f, 0.f);
        const float* bp = Bm + (size_t)(k0 + bRow) * Nn + bc;
        if (bc + 3 < Nn) {
            bv = *(const float4*)bp;
        } else {
            if (bc + 0 < Nn) bv.x = bp[0];
            if (bc + 1 < Nn) bv.y = bp[1];
            if (bc + 2 < Nn) bv.z = bp[2];
        }
        *(float4*)&Bs[bRow][bCol] = bv;
        __syncthreads();
#pragma unroll
        for (int kk = 0; kk < 16; kk++) {
            float4 ra = *(const float4*)&As[kk][ty << 2];
            float4 rb = *(const float4*)&Bs[kk][tx << 2];
            float a[4] = {ra.x, ra.y, ra.z, ra.w};
            float b[4] = {rb.x, rb.y, rb.z, rb.w};
#pragma unroll
            for (int i = 0; i < 4; i++)
#pragma unroll
                for (int j = 0; j < 4; j++) acc[i][j] += a[i] * b[j];
        }
        __syncthreads();
    }
#pragma unroll
    for (int i = 0; i < 4; i++) {
        int r = rowBase + (ty << 2) + i;
#pragma unroll
        for (int j = 0; j < 4; j++) {
            int cc = colBase + (tx << 2) + j;
            if (cc < Nn) C[(size_t)r * Nn + cc] = acc[i][j];
        }
    }
}

// ---------------- depthwise causal conv + transpose to (b,k,h,t) ----------
__global__ void conv_kernel(const float* __restrict__ ck, const float* __restrict__ sscale) {
    __shared__ float tile[32][33];
    int b = blockIdx.z;
    int cBase = blockIdx.x * 32;
    int tBase = blockIdx.y * 32;
    int c = cBase + threadIdx.x;
    float kc[4] = {0.f, 0.f, 0.f, 0.f};
    if (c < ZC) {
#pragma unroll
        for (int j = 0; j < 4; j++) kc[j] = ck[j * ZC + c];
    }
#pragma unroll
    for (int i = 0; i < 4; i++) {
        int t = tBase + threadIdx.y + i * 8;
        float val = 0.0f;
        if (c < ZC) {
#pragma unroll
            for (int j = 0; j < 4; j++) {
                int tt = t - 3 + j;
                if (tt >= 0) val += g_z0[((size_t)(b * LL + tt)) * ZC + c] * kc[j];
            }
        }
        tile[threadIdx.x][threadIdx.y + i * 8] = val;
    }
    __syncthreads();
    int tid = threadIdx.y * 32 + threadIdx.x;
#pragma unroll
    for (int i = 0; i < 4; i++) {
        int idx = tid + i * 256;
        int cl = idx >> 5, tl = idx & 31;
        int cc = cBase + cl;
        int t = tBase + tl;
        if (cc < MEMn) {
            int k = cc >> 6, h = cc & 63;
            g_kval[(((size_t)b * KK + k) * HH + h) * LL + t] = tile[cl][tl];
        } else if (cc < ZC) {
            int k = cc - MEMn;
            float v = tile[cl][tl];
            float lp = fminf(fmaxf(sscale[k] * v, -20.0f), 20.0f);
            float ltw = -g_slope[k] * (float)(LL - 1 - t);
            g_pw[((size_t)b * KK + k) * LL + t] = __expf(lp + ltw);
        }
    }
}

// ---------------- per-chunk partial sums (phase 1 of scan) ----------------
__global__ void __launch_bounds__(LC) chunksum_kernel(const float* __restrict__ tscale) {
    int bk = blockIdx.z;   // b*K + k
    int k = bk % KK;
    int h = blockIdx.y;
    int chunk = blockIdx.x;
    int tl = threadIdx.x;
    int t = chunk * LC + tl;
    int lane = tl & 31, w = tl >> 5;

    float pw = g_pw[(size_t)bk * LL + t];
    float kv = g_kval[(((size_t)bk) * HH + h) * LL + t];
    float kvw = kv * pw;
    float tanhv = tanhf(tscale[k] * kv);
    int thb = (k * HH + h) * MM;
    float vals[9];
#pragma unroll
    for (int m = 0; m < MM; m++) {
        float s, c2;
        __sincosf(tanhv * g_theta[thb + m], &s, &c2);
        vals[2 * m] = kvw * c2;
        vals[2 * m + 1] = kvw * s;
    }
    vals[8] = pw;

    __shared__ float red[9][8];
#pragma unroll
    for (int j = 0; j < 9; j++) {
        float x = vals[j];
#pragma unroll
        for (int d = 16; d > 0; d >>= 1) x += __shfl_down_sync(0xffffffffu, x, d);
        if (lane == 0) red[j][w] = x;
    }
    __syncthreads();
    if (tl < 9) {
        float s = 0.0f;
#pragma unroll
        for (int ww = 0; ww < 8; ww++) s += red[tl][ww];
        if (tl < 8) {
            int m = tl >> 1, ri = tl & 1;
            size_t ch = ((size_t)bk * HH + h) * MM + m;
            g_csum[(ch * 2 + ri) * NCH + chunk] = s;
        } else if (h == 0) {
            g_dsum[(size_t)bk * NCH + chunk] = s;
        }
    }
}

// ---------------- exclusive scan of chunk sums (phase 2) ----------------
__global__ void scanoff_kernel() {
    int idx = blockIdx.x * 256 + threadIdx.x;
    const int NRI = BB * KK * HH * MM * 2;
    if (idx < NRI) {
        float run = 0.0f;
#pragma unroll
        for (int c = 0; c < NCH; c++) {
            float x = g_csum[(size_t)idx * NCH + c];
            g_coff[(size_t)idx * NCH + c] = run;
            run += x;
        }
    } else if (idx < NRI + BB * KK) {
        int d = idx - NRI;
        float run = 0.0f;
#pragma unroll
        for (int c = 0; c < NCH; c++) {
            float x = g_dsum[(size_t)d * NCH + c];
            g_doff[(size_t)d * NCH + c] = run;
            run += x;
        }
    }
}

// ---------------- fused in-chunk scan + q-combine (phase 3) ----------------
__global__ void __launch_bounds__(LC) phase3_kernel(const float* __restrict__ tscale,
                                                    const float* __restrict__ nscale) {
    int b = blockIdx.z, k = blockIdx.y, chunk = blockIdx.x;
    int tl = threadIdx.x, lane = tl & 31, w = tl >> 5;
    int t = chunk * LC + tl;
    int bk = b * KK + k;
    __shared__ float agg[8][9];

    // inclusive scan of den (p_w)
    float pw = g_pw[(size_t)bk * LL + t];
    float x = pw;
#pragma unroll
    for (int d = 1; d < 32; d <<= 1) {
        float n = __shfl_up_sync(0xffffffffu, x, d);
        if (lane >= d) x += n;
    }
    if (lane == 31) agg[w][0] = x;
    __syncthreads();
    float doff = g_doff[(size_t)bk * NCH + chunk];
    for (int ww = 0; ww < w; ww++) doff += agg[ww][0];
    float den = doff + x;
    float invden = 1.0f / fmaxf(den, 1e-4f);
    __syncthreads();

    int kq = k >> 1;
    const float* qrow = g_q + ((size_t)(b * LL + t) * KQn + kq) * (HH * MM * 2);
    float ts = tscale[k];
    size_t kvbase = ((size_t)bk * HH) * LL + t;
    size_t Arow = ((size_t)k * BL + (size_t)(b * LL + t)) * 128;
    size_t chb_base = ((size_t)bk * HH) * MM;
    int thb_base = (k * HH) * MM;

    for (int h = 0; h < HH; h++) {
        float kv = g_kval[kvbase + (size_t)h * LL];
        float kvw = kv * pw;
        float tanhv = tanhf(ts * kv);
        float4 qa = *(const float4*)(qrow + h * 8);
        float4 qb = *(const float4*)(qrow + h * 8 + 4);
        int thb = thb_base + h * MM;
        size_t chb = chb_base + (size_t)h * MM;
        float v[8];
#pragma unroll
        for (int m = 0; m < MM; m++) {
            float s, c2;
            __sincosf(tanhv * g_theta[thb + m], &s, &c2);
            v[2 * m] = kvw * c2;
            v[2 * m + 1] = kvw * s;
        }
        // 8 inclusive scans over the 256-thread block
#pragma unroll
        for (int j = 0; j < 8; j++) {
            float y = v[j];
#pragma unroll
            for (int d = 1; d < 32; d <<= 1) {
                float n = __shfl_up_sync(0xffffffffu, y, d);
                if (lane >= d) y += n;
            }
            v[j] = y;
        }
        if (lane == 31) {
#pragma unroll
            for (int j = 0; j < 8; j++) agg[w][j] = v[j];
        }
        __syncthreads();
        float woff[8];
#pragma unroll
        for (int j = 0; j < 8; j++) woff[j] = 0.0f;
        for (int ww = 0; ww < w; ww++) {
#pragma unroll
            for (int j = 0; j < 8; j++) woff[j] += agg[ww][j];
        }
        float qr[4] = {qa.x, qa.z, qb.x, qb.z};
        float qi[4] = {qa.y, qa.w, qb.y, qb.w};
        float accre = 0.0f, accim = 0.0f;
#pragma unroll
        for (int m = 0; m < MM; m++) {
            float offre = g_coff[((chb + m) * 2 + 0) * NCH + chunk];
            float offim = g_coff[((chb + m) * 2 + 1) * NCH + chunk];
            float sre = (offre + woff[2 * m] + v[2 * m]) * invden;
            float sim = (offim + woff[2 * m + 1] + v[2 * m + 1]) * invden;
            float wg = g_wint[thb + m];
            accre += (sre * qr[m] + sim * qi[m]) * wg;
            accim += (sim * qr[m] - sre * qi[m]) * wg;
        }
        float ns = nscale[k * HH + h];
        g_A[Arow + h] = accre * ns;
        g_A[Arow + 64 + h] = accim * ns;
        __syncthreads();
    }
}

// ---------------- gate/highway/silu epilogue ----------------
__global__ void combine2_kernel(const float* __restrict__ gate_b,
                                const float* __restrict__ hscale) {
    int idx = blockIdx.x * 256 + threadIdx.x;
    if (idx >= BL * 2304) return;
    int row = idx / 2304, n = idx % 2304;
    int k = n / EXPn, e = n % EXPn;
    size_t sb = ((size_t)k * BL + row) * DSWn;
    float sv = g_yspec[sb + e];
    float sg = g_yspec[sb + EXPn + e];
    size_t db = (size_t)row * 4608 + (size_t)k * DSWn;
    float dv = g_ydir[db + e];
    float dg = g_ydir[db + EXPn + e];
    float gate = 1.0f / (1.0f + __expf(-(g_gatelin[(size_t)row * KK + k] + gate_b[k])));
    float hs = hscale[k];
    float val = sv * gate + dv * hs;
    float gt = sg * gate + dg * hs;
    g_yfin[(size_t)row * 2304 + n] = val * gt / (1.0f + __expf(-gt));
}

// ---------------- host launcher ----------------
extern "C" void kernel_launch(void* const* d_in, const int* in_sizes, int n_in,
                              void* d_out, int out_size) {
    const float* x = (const float*)d_in[0];
    const float* W_mem = (const float*)d_in[1];
    const float* conv_k = (const float*)d_in[2];
    const float* W_q = (const float*)d_in[3];
    const float* theta_raw = (const float*)d_in[4];
    const float* decay = (const float*)d_in[5];
    const float* sscale = (const float*)d_in[6];
    const float* tscale = (const float*)d_in[7];
    const float* W_re = (const float*)d_in[8];
    const float* W_im = (const float*)d_in[9];
    const float* nscale = (const float*)d_in[10];
    const float* gate_W = (const float*)d_in[11];
    const float* gate_b = (const float*)d_in[12];
    const float* skip_down = (const float*)d_in[13];
    const float* skip_up = (const float*)d_in[14];
    const float* hscale = (const float*)d_in[15];
    const float* out_W = (const float*)d_in[16];

    float *z0, *q, *gl, *lat, *ydir, *A, *wcat, *yspec, *yfin;
    cudaGetSymbolAddress((void**)&z0, g_z0);
    cudaGetSymbolAddress((void**)&q, g_q);
    cudaGetSymbolAddress((void**)&gl, g_gatelin);
    cudaGetSymbolAddress((void**)&lat, g_lat);
    cudaGetSymbolAddress((void**)&ydir, g_ydir);
    cudaGetSymbolAddress((void**)&A, g_A);
    cudaGetSymbolAddress((void**)&wcat, g_wcat);
    cudaGetSymbolAddress((void**)&yspec, g_yspec);
    cudaGetSymbolAddress((void**)&yfin, g_yfin);

    precompute_kernel<<<3, 256>>>(theta_raw, decay);
    wcat_kernel<<<(KK * 128 * DSWn + 255) / 256, 256>>>(W_re, W_im);

    // z0 = x @ W_mem  (4096 x 780, K=768)
    sgemm_kernel<<<dim3(13, 64, 1), 256>>>(x, W_mem, z0, ZC, DD, 0, 0, 0);
    // q = x @ W_q  (4096 x 3072, K=768)
    sgemm_kernel<<<dim3(48, 64, 1), 256>>>(x, W_q, q, 3072, DD, 0, 0, 0);
    // gate_lin = x @ gate_W  (4096 x 12, K=768)
    sgemm_kernel<<<dim3(1, 64, 1), 256>>>(x, gate_W, gl, KK, DD, 0, 0, 0);
    // lat = x @ skip_down  (4096 x 192, K=768)
    sgemm_kernel<<<dim3(3, 64, 1), 256>>>(x, skip_down, lat, LATn, DD, 0, 0, 0);
    // ydir = lat @ skip_up  (4096 x 4608, K=192)
    sgemm_kernel<<<dim3(72, 64, 1), 256>>>(lat, skip_up, ydir, 4608, LATn, 0, 0, 0);

    conv_kernel<<<dim3(25, 64, BB), dim3(32, 8)>>>(conv_k, sscale);
    chunksum_kernel<<<dim3(NCH, HH, BB * KK), LC>>>(tscale);
    scanoff_kernel<<<(BB * KK * HH * MM * 2 + BB * KK + 255) / 256, 256>>>();
    phase3_kernel<<<dim3(NCH, KK, BB), LC>>>(tscale, nscale);

    // yspec_pre[k] = A_k (4096x128) @ Wcat_k (128x384), batched over k
    sgemm_kernel<<<dim3(6, 64, KK), 256>>>(A, wcat, yspec, DSWn, 128,
                                           (size_t)BL * 128, (size_t)128 * DSWn,
                                           (size_t)BL * DSWn);

    combine2_kernel<<<((size_t)BL * 2304 + 255) / 256, 256>>>(gate_b, hscale);

    // out = yfin (4096x2304) @ out_W (2304x768)
    sgemm_kernel<<<dim3(12, 64, 1), 256>>>(yfin, out_W, (float*)d_out, DD, 2304, 0, 0, 0);
}

// round 2
// speedup vs baseline: 1.1366x; 1.1366x over previous
#include <cuda_runtime.h>
#include <math.h>

// ---------------- problem constants ----------------
#define BB 2
#define LL 2048
#define DD 768
#define KK 12
#define KQn 6
#define MM 4
#define HH 64
#define MEMn 768
#define EXPn 192
#define DSWn 384
#define LATn 192
#define BL 4096            // B*L
#define ZC 780             // MEM + K
#define NCH 8
#define LC 256             // chunk length, NCH*LC == LL

// ---------------- scratch (device globals, no allocs) ----------------
__device__ float g_z0[(size_t)BL * ZC];
__device__ float g_q[(size_t)BL * 3072];
__device__ float g_gatelin[(size_t)BL * KK];
__device__ float g_lat[(size_t)BL * LATn];
__device__ float g_ydir[(size_t)BL * 4608];
__device__ float g_kval[(size_t)BB * KK * HH * LL];
__device__ float g_pw[(size_t)BB * KK * LL];
__device__ float g_theta[KK * HH * MM];
__device__ float g_wint[KK * HH * MM];
__device__ float g_slope[KK];
__device__ float g_csum[(size_t)BB * KK * HH * MM * 2 * NCH];
__device__ float g_coff[(size_t)BB * KK * HH * MM * 2 * NCH];
__device__ float g_dsum[(size_t)BB * KK * NCH];
__device__ float g_doff[(size_t)BB * KK * NCH];
__device__ float g_wcat[(size_t)KK * 128 * DSWn];
__device__ float g_A[(size_t)KK * BL * 128];
__device__ float g_yspec[(size_t)KK * BL * DSWn];
__device__ float g_yfin[(size_t)BL * 2304];

__device__ __forceinline__ float softplusf(float x) {
    return (x > 20.0f) ? x : log1pf(__expf(x));
}

// ---------------- precompute theta / w_int / slopes ----------------
__global__ void precompute_kernel(const float* __restrict__ theta_raw,
                                  const float* __restrict__ decay) {
    int tid = blockIdx.x * blockDim.x + threadIdx.x;
    if (tid < KK * HH) {
        float ta[MM];
        float run = 0.0f;
#pragma unroll
        for (int m = 0; m < MM; m++) {
            run += softplusf(theta_raw[tid * MM + m]) + 1e-4f;
            ta[m] = run;
        }
        float total = ta[MM - 1];
        float sc = 2.999f / total;   // rng / total
        float dth[MM - 1];
#pragma unroll
        for (int i = 0; i < MM - 1; i++) dth[i] = (ta[i + 1] - ta[i]) * sc;
#pragma unroll
        for (int m = 0; m < MM; m++) g_theta[tid * MM + m] = 0.001f + ta[m] * sc;
        g_wint[tid * MM + 0] = dth[0] * 0.5f;
        g_wint[tid * MM + 1] = 0.5f * (dth[0] + dth[1]);
        g_wint[tid * MM + 2] = 0.5f * (dth[1] + dth[2]);
        g_wint[tid * MM + 3] = dth[2] * 0.5f;
    }
    if (tid < KK) g_slope[tid] = softplusf(decay[tid]);
}

// ---------------- concat [W_re ; W_im] per k ----------------
__global__ void wcat_kernel(const float* __restrict__ Wre, const float* __restrict__ Wim) {
    int idx = blockIdx.x * 256 + threadIdx.x;
    if (idx >= KK * 128 * DSWn) return;
    int n = idx % DSWn;
    int r = (idx / DSWn) % 128;
    int k = idx / (128 * DSWn);
    g_wcat[idx] = (r < HH) ? Wre[((size_t)k * HH + r) * DSWn + n]
                           : Wim[((size_t)k * HH + (r - HH)) * DSWn + n];
}

// ---------------- 128x128 tile, 8x8 microtile, double-buffered SGEMM -------
// M is always a multiple of 128 (4096). K multiple of 16. N arbitrary (guarded).
__global__ void __launch_bounds__(256, 2) sgemm128_kernel(
    const float* __restrict__ A, const float* __restrict__ Bm, float* __restrict__ C,
    int Nn, int Kk, size_t sA, size_t sB, size_t sC) {
    A += (size_t)blockIdx.z * sA;
    Bm += (size_t)blockIdx.z * sB;
    C += (size_t)blockIdx.z * sC;

    __shared__ float As[2][16][128];   // [k][m] (transposed)
    __shared__ float Bs[2][16][128];   // [k][n]

    const int tid = threadIdx.x;
    const int rowBase = blockIdx.y * 128;
    const int colBase = blockIdx.x * 128;

    // global-load assignments
    const int aRow = tid >> 1;           // 0..127
    const int aCol = (tid & 1) * 8;      // 0 or 8
    const int bRow = tid >> 4;           // 0..15
    const int bCol = (tid & 15) * 8;     // 0..120
    const float* Aptr = A + (size_t)(rowBase + aRow) * Kk + aCol;
    const int bc = colBase + bCol;

    // compute assignments (4+4 split)
    const int tr = (tid >> 4) * 4;       // 0..60
    const int tc = (tid & 15) * 4;       // 0..60

    float acc[8][8];
#pragma unroll
    for (int i = 0; i < 8; i++)
#pragma unroll
        for (int j = 0; j < 8; j++) acc[i][j] = 0.0f;

    const int KT = Kk >> 4;

    float ar[8], br[8];
    // ---- prologue: load tile 0 ----
    {
        float4 a0 = *(const float4*)(Aptr + 0);
        float4 a1 = *(const float4*)(Aptr + 4);
        ar[0]=a0.x; ar[1]=a0.y; ar[2]=a0.z; ar[3]=a0.w;
        ar[4]=a1.x; ar[5]=a1.y; ar[6]=a1.z; ar[7]=a1.w;
        const float* bp = Bm + (size_t)bRow * Nn + bc;
        if (bc + 7 < Nn) {
            float4 b0 = *(const float4*)bp;
            float4 b1 = *(const float4*)(bp + 4);
            br[0]=b0.x; br[1]=b0.y; br[2]=b0.z; br[3]=b0.w;
            br[4]=b1.x; br[5]=b1.y; br[6]=b1.z; br[7]=b1.w;
        } else {
#pragma unroll
            for (int j = 0; j < 8; j++) br[j] = (bc + j < Nn) ? bp[j] : 0.0f;
        }
#pragma unroll
        for (int i = 0; i < 8; i++) As[0][aCol + i][aRow] = ar[i];
        *(float4*)&Bs[0][bRow][bCol] = make_float4(br[0], br[1], br[2], br[3]);
        *(float4*)&Bs[0][bRow][bCol + 4] = make_float4(br[4], br[5], br[6], br[7]);
    }
    __syncthreads();

    int cur = 0;
    for (int kt = 0; kt < KT; kt++) {
        const bool has = (kt + 1) < KT;
        if (has) {
            const int k0 = (kt + 1) << 4;
            float4 a0 = *(const float4*)(Aptr + k0);
            float4 a1 = *(const float4*)(Aptr + k0 + 4);
            ar[0]=a0.x; ar[1]=a0.y; ar[2]=a0.z; ar[3]=a0.w;
            ar[4]=a1.x; ar[5]=a1.y; ar[6]=a1.z; ar[7]=a1.w;
            const float* bp = Bm + (size_t)(k0 + bRow) * Nn + bc;
            if (bc + 7 < Nn) {
                float4 b0 = *(const float4*)bp;
                float4 b1 = *(const float4*)(bp + 4);
                br[0]=b0.x; br[1]=b0.y; br[2]=b0.z; br[3]=b0.w;
                br[4]=b1.x; br[5]=b1.y; br[6]=b1.z; br[7]=b1.w;
            } else {
#pragma unroll
                for (int j = 0; j < 8; j++) br[j] = (bc + j < Nn) ? bp[j] : 0.0f;
            }
        }
#pragma unroll
        for (int kk = 0; kk < 16; kk++) {
            float4 a0 = *(const float4*)&As[cur][kk][tr];
            float4 a1 = *(const float4*)&As[cur][kk][tr + 64];
            float4 b0 = *(const float4*)&Bs[cur][kk][tc];
            float4 b1 = *(const float4*)&Bs[cur][kk][tc + 64];
            float a[8] = {a0.x, a0.y, a0.z, a0.w, a1.x, a1.y, a1.z, a1.w};
            float b[8] = {b0.x, b0.y, b0.z, b0.w, b1.x, b1.y, b1.z, b1.w};
#pragma unroll
            for (int i = 0; i < 8; i++)
#pragma unroll
                for (int j = 0; j < 8; j++) acc[i][j] += a[i] * b[j];
        }
        if (has) {
            const int nxt = cur ^ 1;
#pragma unroll
            for (int i = 0; i < 8; i++) As[nxt][aCol + i][aRow] = ar[i];
            *(float4*)&Bs[nxt][bRow][bCol] = make_float4(br[0], br[1], br[2], br[3]);
            *(float4*)&Bs[nxt][bRow][bCol + 4] = make_float4(br[4], br[5], br[6], br[7]);
            __syncthreads();
            cur = nxt;
        }
    }

    // ---- epilogue ----
    if (colBase + 128 <= Nn) {
#pragma unroll
        for (int i = 0; i < 8; i++) {
            int r = rowBase + tr + (i & 3) + (i >> 2) * 64;
            float* cp = C + (size_t)r * Nn + colBase;
            *(float4*)(cp + tc) = make_float4(acc[i][0], acc[i][1], acc[i][2], acc[i][3]);
            *(float4*)(cp + tc + 64) = make_float4(acc[i][4], acc[i][5], acc[i][6], acc[i][7]);
        }
    } else {
#pragma unroll
        for (int i = 0; i < 8; i++) {
            int r = rowBase + tr + (i & 3) + (i >> 2) * 64;
#pragma unroll
            for (int j = 0; j < 8; j++) {
                int cc = colBase + tc + (j & 3) + (j >> 2) * 64;
                if (cc < Nn) C[(size_t)r * Nn + cc] = acc[i][j];
            }
        }
    }
}

// ---------------- dedicated gate GEMM: N=12, warp-per-row ----------------
__global__ void __launch_bounds__(256) gate_kernel(const float* __restrict__ x,
                                                   const float* __restrict__ gW) {
    int row = blockIdx.x * 8 + (threadIdx.x >> 5);
    int lane = threadIdx.x & 31;
    const float* xr = x + (size_t)row * DD;
    float acc[KK];
#pragma unroll
    for (int j = 0; j < KK; j++) acc[j] = 0.0f;
    for (int k = lane; k < DD; k += 32) {
        float xv = xr[k];
        const float* gp = gW + (size_t)k * KK;
#pragma unroll
        for (int j = 0; j < KK; j++) acc[j] += xv * gp[j];
    }
#pragma unroll
    for (int j = 0; j < KK; j++) {
        float v = acc[j];
#pragma unroll
        for (int d = 16; d > 0; d >>= 1) v += __shfl_down_sync(0xffffffffu, v, d);
        if (lane == 0) g_gatelin[(size_t)row * KK + j] = v;
    }
}

// ---------------- depthwise causal conv + transpose to (b,k,h,t) ----------
__global__ void conv_kernel(const float* __restrict__ ck, const float* __restrict__ sscale) {
    __shared__ float tile[32][33];
    int b = blockIdx.z;
    int cBase = blockIdx.x * 32;
    int tBase = blockIdx.y * 32;
    int c = cBase + threadIdx.x;
    float kc[4] = {0.f, 0.f, 0.f, 0.f};
    if (c < ZC) {
#pragma unroll
        for (int j = 0; j < 4; j++) kc[j] = ck[j * ZC + c];
    }
#pragma unroll
    for (int i = 0; i < 4; i++) {
        int t = tBase + threadIdx.y + i * 8;
        float val = 0.0f;
        if (c < ZC) {
#pragma unroll
            for (int j = 0; j < 4; j++) {
                int tt = t - 3 + j;
                if (tt >= 0) val += g_z0[((size_t)(b * LL + tt)) * ZC + c] * kc[j];
            }
        }
        tile[threadIdx.x][threadIdx.y + i * 8] = val;
    }
    __syncthreads();
    int tid = threadIdx.y * 32 + threadIdx.x;
#pragma unroll
    for (int i = 0; i < 4; i++) {
        int idx = tid + i * 256;
        int cl = idx >> 5, tl = idx & 31;
        int cc = cBase + cl;
        int t = tBase + tl;
        if (cc < MEMn) {
            int k = cc >> 6, h = cc & 63;
            g_kval[(((size_t)b * KK + k) * HH + h) * LL + t] = tile[cl][tl];
        } else if (cc < ZC) {
            int k = cc - MEMn;
            float v = tile[cl][tl];
            float lp = fminf(fmaxf(sscale[k] * v, -20.0f), 20.0f);
            float ltw = -g_slope[k] * (float)(LL - 1 - t);
            g_pw[((size_t)b * KK + k) * LL + t] = __expf(lp + ltw);
        }
    }
}

// ---------------- per-chunk partial sums (phase 1 of scan) ----------------
__global__ void __launch_bounds__(LC) chunksum_kernel(const float* __restrict__ tscale) {
    int bk = blockIdx.z;   // b*K + k
    int k = bk % KK;
    int h = blockIdx.y;
    int chunk = blockIdx.x;
    int tl = threadIdx.x;
    int t = chunk * LC + tl;
    int lane = tl & 31, w = tl >> 5;

    float pw = g_pw[(size_t)bk * LL + t];
    float kv = g_kval[(((size_t)bk) * HH + h) * LL + t];
    float kvw = kv * pw;
    float tanhv = tanhf(tscale[k] * kv);
    int thb = (k * HH + h) * MM;
    float vals[9];
#pragma unroll
    for (int m = 0; m < MM; m++) {
        float s, c2;
        __sincosf(tanhv * g_theta[thb + m], &s, &c2);
        vals[2 * m] = kvw * c2;
        vals[2 * m + 1] = kvw * s;
    }
    vals[8] = pw;

    __shared__ float red[9][8];
#pragma unroll
    for (int j = 0; j < 9; j++) {
        float x = vals[j];
#pragma unroll
        for (int d = 16; d > 0; d >>= 1) x += __shfl_down_sync(0xffffffffu, x, d);
        if (lane == 0) red[j][w] = x;
    }
    __syncthreads();
    if (tl < 9) {
        float s = 0.0f;
#pragma unroll
        for (int ww = 0; ww < 8; ww++) s += red[tl][ww];
        if (tl < 8) {
            int m = tl >> 1, ri = tl & 1;
            size_t ch = ((size_t)bk * HH + h) * MM + m;
            g_csum[(ch * 2 + ri) * NCH + chunk] = s;
        } else if (h == 0) {
            g_dsum[(size_t)bk * NCH + chunk] = s;
        }
    }
}

// ---------------- exclusive scan of chunk sums (phase 2) ----------------
__global__ void scanoff_kernel() {
    int idx = blockIdx.x * 256 + threadIdx.x;
    const int NRI = BB * KK * HH * MM * 2;
    if (idx < NRI) {
        float run = 0.0f;
#pragma unroll
        for (int c = 0; c < NCH; c++) {
            float x = g_csum[(size_t)idx * NCH + c];
            g_coff[(size_t)idx * NCH + c] = run;
            run += x;
        }
    } else if (idx < NRI + BB * KK) {
        int d = idx - NRI;
        float run = 0.0f;
#pragma unroll
        for (int c = 0; c < NCH; c++) {
            float x = g_dsum[(size_t)d * NCH + c];
            g_doff[(size_t)d * NCH + c] = run;
            run += x;
        }
    }
}

// ---------------- fused in-chunk scan + q-combine (phase 3) ----------------
__global__ void __launch_bounds__(LC) phase3_kernel(const float* __restrict__ tscale,
                                                    const float* __restrict__ nscale) {
    int b = blockIdx.z, k = blockIdx.y, chunk = blockIdx.x;
    int tl = threadIdx.x, lane = tl & 31, w = tl >> 5;
    int t = chunk * LC + tl;
    int bk = b * KK + k;
    __shared__ float agg[8][9];

    // inclusive scan of den (p_w)
    float pw = g_pw[(size_t)bk * LL + t];
    float x = pw;
#pragma unroll
    for (int d = 1; d < 32; d <<= 1) {
        float n = __shfl_up_sync(0xffffffffu, x, d);
        if (lane >= d) x += n;
    }
    if (lane == 31) agg[w][0] = x;
    __syncthreads();
    float doff = g_doff[(size_t)bk * NCH + chunk];
    for (int ww = 0; ww < w; ww++) doff += agg[ww][0];
    float den = doff + x;
    float invden = 1.0f / fmaxf(den, 1e-4f);
    __syncthreads();

    int kq = k >> 1;
    const float* qrow = g_q + ((size_t)(b * LL + t) * KQn + kq) * (HH * MM * 2);
    float ts = tscale[k];
    size_t kvbase = ((size_t)bk * HH) * LL + t;
    size_t Arow = ((size_t)k * BL + (size_t)(b * LL + t)) * 128;
    size_t chb_base = ((size_t)bk * HH) * MM;
    int thb_base = (k * HH) * MM;

    for (int h = 0; h < HH; h++) {
        float kv = g_kval[kvbase + (size_t)h * LL];
        float kvw = kv * pw;
        float tanhv = tanhf(ts * kv);
        float4 qa = *(const float4*)(qrow + h * 8);
        float4 qb = *(const float4*)(qrow + h * 8 + 4);
        int thb = thb_base + h * MM;
        size_t chb = chb_base + (size_t)h * MM;
        float v[8];
#pragma unroll
        for (int m = 0; m < MM; m++) {
            float s, c2;
            __sincosf(tanhv * g_theta[thb + m], &s, &c2);
            v[2 * m] = kvw * c2;
            v[2 * m + 1] = kvw * s;
        }
        // 8 inclusive scans over the 256-thread block
#pragma unroll
        for (int j = 0; j < 8; j++) {
            float y = v[j];
#pragma unroll
            for (int d = 1; d < 32; d <<= 1) {
                float n = __shfl_up_sync(0xffffffffu, y, d);
                if (lane >= d) y += n;
            }
            v[j] = y;
        }
        if (lane == 31) {
#pragma unroll
            for (int j = 0; j < 8; j++) agg[w][j] = v[j];
        }
        __syncthreads();
        float woff[8];
#pragma unroll
        for (int j = 0; j < 8; j++) woff[j] = 0.0f;
        for (int ww = 0; ww < w; ww++) {
#pragma unroll
            for (int j = 0; j < 8; j++) woff[j] += agg[ww][j];
        }
        float qr[4] = {qa.x, qa.z, qb.x, qb.z};
        float qi[4] = {qa.y, qa.w, qb.y, qb.w};
        float accre = 0.0f, accim = 0.0f;
#pragma unroll
        for (int m = 0; m < MM; m++) {
            float offre = g_coff[((chb + m) * 2 + 0) * NCH + chunk];
            float offim = g_coff[((chb + m) * 2 + 1) * NCH + chunk];
            float sre = (offre + woff[2 * m] + v[2 * m]) * invden;
            float sim = (offim + woff[2 * m + 1] + v[2 * m + 1]) * invden;
            float wg = g_wint[thb + m];
            accre += (sre * qr[m] + sim * qi[m]) * wg;
            accim += (sim * qr[m] - sre * qi[m]) * wg;
        }
        float ns = nscale[k * HH + h];
        g_A[Arow + h] = accre * ns;
        g_A[Arow + 64 + h] = accim * ns;
        __syncthreads();
    }
}

// ---------------- gate/highway/silu epilogue ----------------
__global__ void combine2_kernel(const float* __restrict__ gate_b,
                                const float* __restrict__ hscale) {
    int idx = blockIdx.x * 256 + threadIdx.x;
    if (idx >= BL * 2304) return;
    int row = idx / 2304, n = idx % 2304;
    int k = n / EXPn, e = n % EXPn;
    size_t sb = ((size_t)k * BL + row) * DSWn;
    float sv = g_yspec[sb + e];
    float sg = g_yspec[sb + EXPn + e];
    size_t db = (size_t)row * 4608 + (size_t)k * DSWn;
    float dv = g_ydir[db + e];
    float dg = g_ydir[db + EXPn + e];
    float gate = 1.0f / (1.0f + __expf(-(g_gatelin[(size_t)row * KK + k] + gate_b[k])));
    float hs = hscale[k];
    float val = sv * gate + dv * hs;
    float gt = sg * gate + dg * hs;
    g_yfin[(size_t)row * 2304 + n] = val * gt / (1.0f + __expf(-gt));
}

// ---------------- host launcher ----------------
extern "C" void kernel_launch(void* const* d_in, const int* in_sizes, int n_in,
                              void* d_out, int out_size) {
    const float* x = (const float*)d_in[0];
    const float* W_mem = (const float*)d_in[1];
    const float* conv_k = (const float*)d_in[2];
    const float* W_q = (const float*)d_in[3];
    const float* theta_raw = (const float*)d_in[4];
    const float* decay = (const float*)d_in[5];
    const float* sscale = (const float*)d_in[6];
    const float* tscale = (const float*)d_in[7];
    const float* W_re = (const float*)d_in[8];
    const float* W_im = (const float*)d_in[9];
    const float* nscale = (const float*)d_in[10];
    const float* gate_W = (const float*)d_in[11];
    const float* gate_b = (const float*)d_in[12];
    const float* skip_down = (const float*)d_in[13];
    const float* skip_up = (const float*)d_in[14];
    const float* hscale = (const float*)d_in[15];
    const float* out_W = (const float*)d_in[16];

    float *z0, *q, *lat, *ydir, *A, *wcat, *yspec, *yfin;
    cudaGetSymbolAddress((void**)&z0, g_z0);
    cudaGetSymbolAddress((void**)&q, g_q);
    cudaGetSymbolAddress((void**)&lat, g_lat);
    cudaGetSymbolAddress((void**)&ydir, g_ydir);
    cudaGetSymbolAddress((void**)&A, g_A);
    cudaGetSymbolAddress((void**)&wcat, g_wcat);
    cudaGetSymbolAddress((void**)&yspec, g_yspec);
    cudaGetSymbolAddress((void**)&yfin, g_yfin);

    precompute_kernel<<<3, 256>>>(theta_raw, decay);
    wcat_kernel<<<(KK * 128 * DSWn + 255) / 256, 256>>>(W_re, W_im);

    // z0 = x @ W_mem  (4096 x 780, K=768)
    sgemm128_kernel<<<dim3(7, 32, 1), 256>>>(x, W_mem, z0, ZC, DD, 0, 0, 0);
    // q = x @ W_q  (4096 x 3072, K=768)
    sgemm128_kernel<<<dim3(24, 32, 1), 256>>>(x, W_q, q, 3072, DD, 0, 0, 0);
    // gate_lin = x @ gate_W  (4096 x 12, K=768)
    gate_kernel<<<BL / 8, 256>>>(x, gate_W);
    // lat = x @ skip_down  (4096 x 192, K=768)
    sgemm128_kernel<<<dim3(2, 32, 1), 256>>>(x, skip_down, lat, LATn, DD, 0, 0, 0);
    // ydir = lat @ skip_up  (4096 x 4608, K=192)
    sgemm128_kernel<<<dim3(36, 32, 1), 256>>>(lat, skip_up, ydir, 4608, LATn, 0, 0, 0);

    conv_kernel<<<dim3(25, 64, BB), dim3(32, 8)>>>(conv_k, sscale);
    chunksum_kernel<<<dim3(NCH, HH, BB * KK), LC>>>(tscale);
    scanoff_kernel<<<(BB * KK * HH * MM * 2 + BB * KK + 255) / 256, 256>>>();
    phase3_kernel<<<dim3(NCH, KK, BB), LC>>>(tscale, nscale);

    // yspec_pre[k] = A_k (4096x128) @ Wcat_k (128x384), batched over k
    sgemm128_kernel<<<dim3(3, 32, KK), 256>>>(A, wcat, yspec, DSWn, 128,
                                              (size_t)BL * 128, (size_t)128 * DSWn,
                                              (size_t)BL * DSWn);

    combine2_kernel<<<((size_t)BL * 2304 + 255) / 256, 256>>>(gate_b, hscale);

    // out = yfin (4096x2304) @ out_W (2304x768)
    sgemm128_kernel<<<dim3(6, 32, 1), 256>>>(yfin, out_W, (float*)d_out, DD, 2304, 0, 0, 0);
}

// round 3
// speedup vs baseline: 2.1591x; 1.8997x over previous
#include <cuda_runtime.h>
#include <math.h>
#include <stdint.h>

// ---------------- problem constants ----------------
#define BB 2
#define LL 2048
#define DD 768
#define KK 12
#define KQn 6
#define MM 4
#define HH 64
#define MEMn 768
#define EXPn 192
#define DSWn 384
#define LATn 192
#define BL 4096            // B*L
#define ZC 780             // MEM + K
#define NCH 8
#define LC 256             // chunk length, NCH*LC == LL

// ---------------- scratch (device globals, no allocs) ----------------
__device__ float g_z0[(size_t)BL * ZC];
__device__ float g_q[(size_t)BL * 3072];
__device__ float g_gatelin[(size_t)BL * KK];
__device__ float g_lat[(size_t)BL * LATn];
__device__ float g_ydir[(size_t)BL * 4608];
__device__ float g_kval[(size_t)BB * KK * HH * LL];
__device__ float g_pw[(size_t)BB * KK * LL];
__device__ float g_theta[KK * HH * MM];
__device__ float g_wint[KK * HH * MM];
__device__ float g_slope[KK];
__device__ float g_csum[(size_t)BB * KK * HH * MM * 2 * NCH];
__device__ float g_coff[(size_t)BB * KK * HH * MM * 2 * NCH];
__device__ float g_dsum[(size_t)BB * KK * NCH];
__device__ float g_doff[(size_t)BB * KK * NCH];
__device__ float g_wcat[(size_t)KK * 128 * DSWn];
__device__ float g_A[(size_t)KK * BL * 128];
__device__ float g_yspec[(size_t)KK * BL * DSWn];
__device__ float g_yfin[(size_t)BL * 2304];

__device__ __forceinline__ float softplusf(float x) {
    return (x > 20.0f) ? x : log1pf(__expf(x));
}

__device__ __forceinline__ float to_tf32(float x) {
    uint32_t u;
    asm("cvt.rna.tf32.f32 %0, %1;" : "=r"(u) : "f"(x));
    return __uint_as_float(u);
}

// ---------------- precompute theta / w_int / slopes ----------------
__global__ void precompute_kernel(const float* __restrict__ theta_raw,
                                  const float* __restrict__ decay) {
    int tid = blockIdx.x * blockDim.x + threadIdx.x;
    if (tid < KK * HH) {
        float ta[MM];
        float run = 0.0f;
#pragma unroll
        for (int m = 0; m < MM; m++) {
            run += softplusf(theta_raw[tid * MM + m]) + 1e-4f;
            ta[m] = run;
        }
        float total = ta[MM - 1];
        float sc = 2.999f / total;   // rng / total
        float dth[MM - 1];
#pragma unroll
        for (int i = 0; i < MM - 1; i++) dth[i] = (ta[i + 1] - ta[i]) * sc;
#pragma unroll
        for (int m = 0; m < MM; m++) g_theta[tid * MM + m] = 0.001f + ta[m] * sc;
        g_wint[tid * MM + 0] = dth[0] * 0.5f;
        g_wint[tid * MM + 1] = 0.5f * (dth[0] + dth[1]);
        g_wint[tid * MM + 2] = 0.5f * (dth[1] + dth[2]);
        g_wint[tid * MM + 3] = dth[2] * 0.5f;
    }
    if (tid < KK) g_slope[tid] = softplusf(decay[tid]);
}

// ---------------- concat [W_re ; W_im] per k ----------------
__global__ void wcat_kernel(const float* __restrict__ Wre, const float* __restrict__ Wim) {
    int idx = blockIdx.x * 256 + threadIdx.x;
    if (idx >= KK * 128 * DSWn) return;
    int n = idx % DSWn;
    int r = (idx / DSWn) % 128;
    int k = idx / (128 * DSWn);
    g_wcat[idx] = (r < HH) ? Wre[((size_t)k * HH + r) * DSWn + n]
                           : Wim[((size_t)k * HH + (r - HH)) * DSWn + n];
}

// ---------------- tf32 tensor-core GEMM, 128x128 tile, 8 warps -----------
// C[M,N] = A[M,K] @ B[K,N]. M multiple of 128, K multiple of 16, N guarded.
__global__ void __launch_bounds__(256, 2) tgemm_kernel(
    const float* __restrict__ A, const float* __restrict__ Bm, float* __restrict__ C,
    int Nn, int Kk, size_t sA, size_t sB, size_t sC) {
    A += (size_t)blockIdx.z * sA;
    Bm += (size_t)blockIdx.z * sB;
    C += (size_t)blockIdx.z * sC;

    __shared__ float As[2][16][136];   // [k][m], padded: 136 mod 32 = 8 -> conflict-free frag loads
    __shared__ float Bs[2][16][136];   // [k][n]

    const int tid = threadIdx.x;
    const int lane = tid & 31;
    const int wid = tid >> 5;
    const int wm = wid >> 2;            // 0..1  (64 rows each)
    const int wn = wid & 3;             // 0..3  (32 cols each)
    const int g = lane >> 2;            // group id 0..7
    const int tc4 = lane & 3;           // 0..3

    const int rowBase = blockIdx.y * 128;
    const int colBase = blockIdx.x * 128;

    // global-load assignments
    const int aRow = tid >> 1;           // 0..127
    const int aCol = (tid & 1) * 8;      // 0 or 8
    const int bRow = tid >> 4;           // 0..15
    const int bCol = (tid & 15) * 8;     // 0..120
    const float* Aptr = A + (size_t)(rowBase + aRow) * Kk + aCol;
    const int bc = colBase + bCol;

    // accumulators: [mt][nt][4]
    float acc[4][4][4];
#pragma unroll
    for (int i = 0; i < 4; i++)
#pragma unroll
        for (int j = 0; j < 4; j++)
#pragma unroll
            for (int r = 0; r < 4; r++) acc[i][j][r] = 0.0f;

    const int KT = Kk >> 4;
    float ar[8], br[8];

    // ---- prologue: load tile 0 ----
    {
        float4 a0 = *(const float4*)(Aptr + 0);
        float4 a1 = *(const float4*)(Aptr + 4);
        ar[0]=a0.x; ar[1]=a0.y; ar[2]=a0.z; ar[3]=a0.w;
        ar[4]=a1.x; ar[5]=a1.y; ar[6]=a1.z; ar[7]=a1.w;
        const float* bp = Bm + (size_t)bRow * Nn + bc;
        if (bc + 7 < Nn) {
            float4 b0 = *(const float4*)bp;
            float4 b1 = *(const float4*)(bp + 4);
            br[0]=b0.x; br[1]=b0.y; br[2]=b0.z; br[3]=b0.w;
            br[4]=b1.x; br[5]=b1.y; br[6]=b1.z; br[7]=b1.w;
        } else {
#pragma unroll
            for (int j = 0; j < 8; j++) br[j] = (bc + j < Nn) ? bp[j] : 0.0f;
        }
#pragma unroll
        for (int i = 0; i < 8; i++) As[0][aCol + i][aRow] = to_tf32(ar[i]);
#pragma unroll
        for (int i = 0; i < 8; i++) br[i] = to_tf32(br[i]);
        *(float4*)&Bs[0][bRow][bCol] = make_float4(br[0], br[1], br[2], br[3]);
        *(float4*)&Bs[0][bRow][bCol + 4] = make_float4(br[4], br[5], br[6], br[7]);
    }
    __syncthreads();

    int cur = 0;
    for (int kt = 0; kt < KT; kt++) {
        const bool has = (kt + 1) < KT;
        if (has) {
            const int k0 = (kt + 1) << 4;
            float4 a0 = *(const float4*)(Aptr + k0);
            float4 a1 = *(const float4*)(Aptr + k0 + 4);
            ar[0]=a0.x; ar[1]=a0.y; ar[2]=a0.z; ar[3]=a0.w;
            ar[4]=a1.x; ar[5]=a1.y; ar[6]=a1.z; ar[7]=a1.w;
            const float* bp = Bm + (size_t)(k0 + bRow) * Nn + bc;
            if (bc + 7 < Nn) {
                float4 b0 = *(const float4*)bp;
                float4 b1 = *(const float4*)(bp + 4);
                br[0]=b0.x; br[1]=b0.y; br[2]=b0.z; br[3]=b0.w;
                br[4]=b1.x; br[5]=b1.y; br[6]=b1.z; br[7]=b1.w;
            } else {
#pragma unroll
                for (int j = 0; j < 8; j++) br[j] = (bc + j < Nn) ? bp[j] : 0.0f;
            }
        }
        // ---- compute 2 k-steps of 8 ----
#pragma unroll
        for (int ks = 0; ks < 2; ks++) {
            const int kk0 = ks * 8;
            const float* Ak0 = &As[cur][kk0 + tc4][0];
            const float* Ak1 = &As[cur][kk0 + tc4 + 4][0];
            const float* Bk0 = &Bs[cur][kk0 + tc4][0];
            const float* Bk1 = &Bs[cur][kk0 + tc4 + 4][0];
            uint32_t af[4][4];
#pragma unroll
            for (int mt = 0; mt < 4; mt++) {
                int m0 = wm * 64 + mt * 16 + g;
                af[mt][0] = __float_as_uint(Ak0[m0]);
                af[mt][1] = __float_as_uint(Ak0[m0 + 8]);
                af[mt][2] = __float_as_uint(Ak1[m0]);
                af[mt][3] = __float_as_uint(Ak1[m0 + 8]);
            }
            uint32_t bf[4][2];
#pragma unroll
            for (int nt = 0; nt < 4; nt++) {
                int n0 = wn * 32 + nt * 8 + g;
                bf[nt][0] = __float_as_uint(Bk0[n0]);
                bf[nt][1] = __float_as_uint(Bk1[n0]);
            }
#pragma unroll
            for (int mt = 0; mt < 4; mt++)
#pragma unroll
                for (int nt = 0; nt < 4; nt++) {
                    asm volatile(
                        "mma.sync.aligned.m16n8k8.row.col.f32.tf32.tf32.f32 "
                        "{%0,%1,%2,%3}, {%4,%5,%6,%7}, {%8,%9}, {%0,%1,%2,%3};"
                        : "+f"(acc[mt][nt][0]), "+f"(acc[mt][nt][1]),
                          "+f"(acc[mt][nt][2]), "+f"(acc[mt][nt][3])
                        : "r"(af[mt][0]), "r"(af[mt][1]), "r"(af[mt][2]), "r"(af[mt][3]),
                          "r"(bf[nt][0]), "r"(bf[nt][1]));
                }
        }
        if (has) {
            const int nxt = cur ^ 1;
#pragma unroll
            for (int i = 0; i < 8; i++) As[nxt][aCol + i][aRow] = to_tf32(ar[i]);
#pragma unroll
            for (int i = 0; i < 8; i++) br[i] = to_tf32(br[i]);
            *(float4*)&Bs[nxt][bRow][bCol] = make_float4(br[0], br[1], br[2], br[3]);
            *(float4*)&Bs[nxt][bRow][bCol + 4] = make_float4(br[4], br[5], br[6], br[7]);
            __syncthreads();
            cur = nxt;
        }
    }

    // ---- epilogue: c0/c1 at (row, n|n+1), c2/c3 at (row+8, n|n+1) ----
#pragma unroll
    for (int mt = 0; mt < 4; mt++) {
        int r0 = rowBase + wm * 64 + mt * 16 + g;
#pragma unroll
        for (int nt = 0; nt < 4; nt++) {
            int cc = colBase + wn * 32 + nt * 8 + tc4 * 2;
            if (cc + 1 < Nn) {
                *(float2*)(C + (size_t)r0 * Nn + cc) = make_float2(acc[mt][nt][0], acc[mt][nt][1]);
                *(float2*)(C + (size_t)(r0 + 8) * Nn + cc) = make_float2(acc[mt][nt][2], acc[mt][nt][3]);
            } else if (cc < Nn) {
                C[(size_t)r0 * Nn + cc] = acc[mt][nt][0];
                C[(size_t)(r0 + 8) * Nn + cc] = acc[mt][nt][2];
            }
        }
    }
}

// ---------------- dedicated gate GEMM: N=12, warp-per-row ----------------
__global__ void __launch_bounds__(256) gate_kernel(const float* __restrict__ x,
                                                   const float* __restrict__ gW) {
    int row = blockIdx.x * 8 + (threadIdx.x >> 5);
    int lane = threadIdx.x & 31;
    const float* xr = x + (size_t)row * DD;
    float acc[KK];
#pragma unroll
    for (int j = 0; j < KK; j++) acc[j] = 0.0f;
    for (int k = lane; k < DD; k += 32) {
        float xv = xr[k];
        const float* gp = gW + (size_t)k * KK;
#pragma unroll
        for (int j = 0; j < KK; j++) acc[j] += xv * gp[j];
    }
#pragma unroll
    for (int j = 0; j < KK; j++) {
        float v = acc[j];
#pragma unroll
        for (int d = 16; d > 0; d >>= 1) v += __shfl_down_sync(0xffffffffu, v, d);
        if (lane == 0) g_gatelin[(size_t)row * KK + j] = v;
    }
}

// ---------------- depthwise causal conv + transpose to (b,k,h,t) ----------
__global__ void conv_kernel(const float* __restrict__ ck, const float* __restrict__ sscale) {
    __shared__ float tile[32][33];
    int b = blockIdx.z;
    int cBase = blockIdx.x * 32;
    int tBase = blockIdx.y * 32;
    int c = cBase + threadIdx.x;
    float kc[4] = {0.f, 0.f, 0.f, 0.f};
    if (c < ZC) {
#pragma unroll
        for (int j = 0; j < 4; j++) kc[j] = ck[j * ZC + c];
    }
#pragma unroll
    for (int i = 0; i < 4; i++) {
        int t = tBase + threadIdx.y + i * 8;
        float val = 0.0f;
        if (c < ZC) {
#pragma unroll
            for (int j = 0; j < 4; j++) {
                int tt = t - 3 + j;
                if (tt >= 0) val += g_z0[((size_t)(b * LL + tt)) * ZC + c] * kc[j];
            }
        }
        tile[threadIdx.x][threadIdx.y + i * 8] = val;
    }
    __syncthreads();
    int tid = threadIdx.y * 32 + threadIdx.x;
#pragma unroll
    for (int i = 0; i < 4; i++) {
        int idx = tid + i * 256;
        int cl = idx >> 5, tl = idx & 31;
        int cc = cBase + cl;
        int t = tBase + tl;
        if (cc < MEMn) {
            int k = cc >> 6, h = cc & 63;
            g_kval[(((size_t)b * KK + k) * HH + h) * LL + t] = tile[cl][tl];
        } else if (cc < ZC) {
            int k = cc - MEMn;
            float v = tile[cl][tl];
            float lp = fminf(fmaxf(sscale[k] * v, -20.0f), 20.0f);
            float ltw = -g_slope[k] * (float)(LL - 1 - t);
            g_pw[((size_t)b * KK + k) * LL + t] = __expf(lp + ltw);
        }
    }
}

// ---------------- per-chunk partial sums (phase 1 of scan) ----------------
__global__ void __launch_bounds__(LC) chunksum_kernel(const float* __restrict__ tscale) {
    int bk = blockIdx.z;   // b*K + k
    int k = bk % KK;
    int h = blockIdx.y;
    int chunk = blockIdx.x;
    int tl = threadIdx.x;
    int t = chunk * LC + tl;
    int lane = tl & 31, w = tl >> 5;

    float pw = g_pw[(size_t)bk * LL + t];
    float kv = g_kval[(((size_t)bk) * HH + h) * LL + t];
    float kvw = kv * pw;
    float tanhv = tanhf(tscale[k] * kv);
    int thb = (k * HH + h) * MM;
    float vals[9];
#pragma unroll
    for (int m = 0; m < MM; m++) {
        float s, c2;
        __sincosf(tanhv * g_theta[thb + m], &s, &c2);
        vals[2 * m] = kvw * c2;
        vals[2 * m + 1] = kvw * s;
    }
    vals[8] = pw;

    __shared__ float red[9][8];
#pragma unroll
    for (int j = 0; j < 9; j++) {
        float x = vals[j];
#pragma unroll
        for (int d = 16; d > 0; d >>= 1) x += __shfl_down_sync(0xffffffffu, x, d);
        if (lane == 0) red[j][w] = x;
    }
    __syncthreads();
    if (tl < 9) {
        float s = 0.0f;
#pragma unroll
        for (int ww = 0; ww < 8; ww++) s += red[tl][ww];
        if (tl < 8) {
            int m = tl >> 1, ri = tl & 1;
            size_t ch = ((size_t)bk * HH + h) * MM + m;
            g_csum[(ch * 2 + ri) * NCH + chunk] = s;
        } else if (h == 0) {
            g_dsum[(size_t)bk * NCH + chunk] = s;
        }
    }
}

// ---------------- exclusive scan of chunk sums (phase 2) ----------------
__global__ void scanoff_kernel() {
    int idx = blockIdx.x * 256 + threadIdx.x;
    const int NRI = BB * KK * HH * MM * 2;
    if (idx < NRI) {
        float run = 0.0f;
#pragma unroll
        for (int c = 0; c < NCH; c++) {
            float x = g_csum[(size_t)idx * NCH + c];
            g_coff[(size_t)idx * NCH + c] = run;
            run += x;
        }
    } else if (idx < NRI + BB * KK) {
        int d = idx - NRI;
        float run = 0.0f;
#pragma unroll
        for (int c = 0; c < NCH; c++) {
            float x = g_dsum[(size_t)d * NCH + c];
            g_doff[(size_t)d * NCH + c] = run;
            run += x;
        }
    }
}

// ---------------- fused in-chunk scan + q-combine (phase 3) ----------------
__global__ void __launch_bounds__(LC) phase3_kernel(const float* __restrict__ tscale,
                                                    const float* __restrict__ nscale) {
    int b = blockIdx.z, k = blockIdx.y, chunk = blockIdx.x;
    int tl = threadIdx.x, lane = tl & 31, w = tl >> 5;
    int t = chunk * LC + tl;
    int bk = b * KK + k;
    __shared__ float agg[8][9];

    // inclusive scan of den (p_w)
    float pw = g_pw[(size_t)bk * LL + t];
    float x = pw;
#pragma unroll
    for (int d = 1; d < 32; d <<= 1) {
        float n = __shfl_up_sync(0xffffffffu, x, d);
        if (lane >= d) x += n;
    }
    if (lane == 31) agg[w][0] = x;
    __syncthreads();
    float doff = g_doff[(size_t)bk * NCH + chunk];
    for (int ww = 0; ww < w; ww++) doff += agg[ww][0];
    float den = doff + x;
    float invden = 1.0f / fmaxf(den, 1e-4f);
    __syncthreads();

    int kq = k >> 1;
    const float* qrow = g_q + ((size_t)(b * LL + t) * KQn + kq) * (HH * MM * 2);
    float ts = tscale[k];
    size_t kvbase = ((size_t)bk * HH) * LL + t;
    size_t Arow = ((size_t)k * BL + (size_t)(b * LL + t)) * 128;
    size_t chb_base = ((size_t)bk * HH) * MM;
    int thb_base = (k * HH) * MM;

    for (int h = 0; h < HH; h++) {
        float kv = g_kval[kvbase + (size_t)h * LL];
        float kvw = kv * pw;
        float tanhv = tanhf(ts * kv);
        float4 qa = *(const float4*)(qrow + h * 8);
        float4 qb = *(const float4*)(qrow + h * 8 + 4);
        int thb = thb_base + h * MM;
        size_t chb = chb_base + (size_t)h * MM;
        float v[8];
#pragma unroll
        for (int m = 0; m < MM; m++) {
            float s, c2;
            __sincosf(tanhv * g_theta[thb + m], &s, &c2);
            v[2 * m] = kvw * c2;
            v[2 * m + 1] = kvw * s;
        }
        // 8 inclusive scans over the 256-thread block
#pragma unroll
        for (int j = 0; j < 8; j++) {
            float y = v[j];
#pragma unroll
            for (int d = 1; d < 32; d <<= 1) {
                float n = __shfl_up_sync(0xffffffffu, y, d);
                if (lane >= d) y += n;
            }
            v[j] = y;
        }
        if (lane == 31) {
#pragma unroll
            for (int j = 0; j < 8; j++) agg[w][j] = v[j];
        }
        __syncthreads();
        float woff[8];
#pragma unroll
        for (int j = 0; j < 8; j++) woff[j] = 0.0f;
        for (int ww = 0; ww < w; ww++) {
#pragma unroll
            for (int j = 0; j < 8; j++) woff[j] += agg[ww][j];
        }
        float qr[4] = {qa.x, qa.z, qb.x, qb.z};
        float qi[4] = {qa.y, qa.w, qb.y, qb.w};
        float accre = 0.0f, accim = 0.0f;
#pragma unroll
        for (int m = 0; m < MM; m++) {
            float offre = g_coff[((chb + m) * 2 + 0) * NCH + chunk];
            float offim = g_coff[((chb + m) * 2 + 1) * NCH + chunk];
            float sre = (offre + woff[2 * m] + v[2 * m]) * invden;
            float sim = (offim + woff[2 * m + 1] + v[2 * m + 1]) * invden;
            float wg = g_wint[thb + m];
            accre += (sre * qr[m] + sim * qi[m]) * wg;
            accim += (sim * qr[m] - sre * qi[m]) * wg;
        }
        float ns = nscale[k * HH + h];
        g_A[Arow + h] = accre * ns;
        g_A[Arow + 64 + h] = accim * ns;
        __syncthreads();
    }
}

// ---------------- gate/highway/silu epilogue ----------------
__global__ void combine2_kernel(const float* __restrict__ gate_b,
                                const float* __restrict__ hscale) {
    int idx = blockIdx.x * 256 + threadIdx.x;
    if (idx >= BL * 2304) return;
    int row = idx / 2304, n = idx % 2304;
    int k = n / EXPn, e = n % EXPn;
    size_t sb = ((size_t)k * BL + row) * DSWn;
    float sv = g_yspec[sb + e];
    float sg = g_yspec[sb + EXPn + e];
    size_t db = (size_t)row * 4608 + (size_t)k * DSWn;
    float dv = g_ydir[db + e];
    float dg = g_ydir[db + EXPn + e];
    float gate = 1.0f / (1.0f + __expf(-(g_gatelin[(size_t)row * KK + k] + gate_b[k])));
    float hs = hscale[k];
    float val = sv * gate + dv * hs;
    float gt = sg * gate + dg * hs;
    g_yfin[(size_t)row * 2304 + n] = val * gt / (1.0f + __expf(-gt));
}

// ---------------- host launcher ----------------
extern "C" void kernel_launch(void* const* d_in, const int* in_sizes, int n_in,
                              void* d_out, int out_size) {
    const float* x = (const float*)d_in[0];
    const float* W_mem = (const float*)d_in[1];
    const float* conv_k = (const float*)d_in[2];
    const float* W_q = (const float*)d_in[3];
    const float* theta_raw = (const float*)d_in[4];
    const float* decay = (const float*)d_in[5];
    const float* sscale = (const float*)d_in[6];
    const float* tscale = (const float*)d_in[7];
    const float* W_re = (const float*)d_in[8];
    const float* W_im = (const float*)d_in[9];
    const float* nscale = (const float*)d_in[10];
    const float* gate_W = (const float*)d_in[11];
    const float* gate_b = (const float*)d_in[12];
    const float* skip_down = (const float*)d_in[13];
    const float* skip_up = (const float*)d_in[14];
    const float* hscale = (const float*)d_in[15];
    const float* out_W = (const float*)d_in[16];

    float *z0, *q, *lat, *ydir, *A, *wcat, *yspec, *yfin;
    cudaGetSymbolAddress((void**)&z0, g_z0);
    cudaGetSymbolAddress((void**)&q, g_q);
    cudaGetSymbolAddress((void**)&lat, g_lat);
    cudaGetSymbolAddress((void**)&ydir, g_ydir);
    cudaGetSymbolAddress((void**)&A, g_A);
    cudaGetSymbolAddress((void**)&wcat, g_wcat);
    cudaGetSymbolAddress((void**)&yspec, g_yspec);
    cudaGetSymbolAddress((void**)&yfin, g_yfin);

    precompute_kernel<<<3, 256>>>(theta_raw, decay);
    wcat_kernel<<<(KK * 128 * DSWn + 255) / 256, 256>>>(W_re, W_im);

    // z0 = x @ W_mem  (4096 x 780, K=768)
    tgemm_kernel<<<dim3(7, 32, 1), 256>>>(x, W_mem, z0, ZC, DD, 0, 0, 0);
    // q = x @ W_q  (4096 x 3072, K=768)
    tgemm_kernel<<<dim3(24, 32, 1), 256>>>(x, W_q, q, 3072, DD, 0, 0, 0);
    // gate_lin = x @ gate_W  (4096 x 12, K=768)
    gate_kernel<<<BL / 8, 256>>>(x, gate_W);
    // lat = x @ skip_down  (4096 x 192, K=768)
    tgemm_kernel<<<dim3(2, 32, 1), 256>>>(x, skip_down, lat, LATn, DD, 0, 0, 0);
    // ydir = lat @ skip_up  (4096 x 4608, K=192)
    tgemm_kernel<<<dim3(36, 32, 1), 256>>>(lat, skip_up, ydir, 4608, LATn, 0, 0, 0);

    conv_kernel<<<dim3(25, 64, BB), dim3(32, 8)>>>(conv_k, sscale);
    chunksum_kernel<<<dim3(NCH, HH, BB * KK), LC>>>(tscale);
    scanoff_kernel<<<(BB * KK * HH * MM * 2 + BB * KK + 255) / 256, 256>>>();
    phase3_kernel<<<dim3(NCH, KK, BB), LC>>>(tscale, nscale);

    // yspec_pre[k] = A_k (4096x128) @ Wcat_k (128x384), batched over k
    tgemm_kernel<<<dim3(3, 32, KK), 256>>>(A, wcat, yspec, DSWn, 128,
                                           (size_t)BL * 128, (size_t)128 * DSWn,
                                           (size_t)BL * DSWn);

    combine2_kernel<<<((size_t)BL * 2304 + 255) / 256, 256>>>(gate_b, hscale);

    // out = yfin (4096x2304) @ out_W (2304x768)
    tgemm_kernel<<<dim3(6, 32, 1), 256>>>(yfin, out_W, (float*)d_out, DD, 2304, 0, 0, 0);
}